// round 7
// baseline (speedup 1.0000x reference)
#include <cuda_runtime.h>
#include <cstdint>

// Problem constants
#define B_ELEMS 4194304          // 2^22 samples
#define NBLK    444              // 148 SMs * 3 CTAs -> one uniform wave at occ 3
#define NTH     256
#define NVEC    (B_ELEMS / 4)    // 2^20 vec4 groups

// Fixed-point (Q32) global accumulators: [center, width, valid, dir]
// Integer addition is exactly associative/commutative -> deterministic across
// replays regardless of block arrival order.
__device__ unsigned long long g_acc[4] = {0ull, 0ull, 0ull, 0ull};
__device__ unsigned int       g_count  = 0;

#define FP_SCALE 4294967296.0    // 2^32

__device__ __forceinline__ void accum_one(float lower, float upper,
                                          float tgt, float prev,
                                          int dt, int pv,
                                          float& s_center, float& s_width,
                                          float& s_valid, float& s_dir) {
    float center = (lower + upper) * 0.5f;
    float d = tgt - center;
    s_center = fmaf(d, d, s_center);
    s_width += (upper - lower);
    s_valid += fmaxf(lower - upper, 0.0f);
    float diff = center - prev;               // pen_up = relu(diff), pen_dn = relu(-diff)
    float sel = (pv == 0) ? diff : -diff;
    s_dir += (dt != 0) ? fmaxf(sel, 0.0f) : 0.0f;
}

// occ=3 -> 85 regs/thread: room for a double-buffered (prefetch) load pipeline.
// While computing iteration i, iteration i+1's 6 vector loads are in flight.
__global__ void __launch_bounds__(NTH, 3)
loss_fused_kernel(const float4* __restrict__ pred,   // (B,2) -> 2 float4 per vec4 of samples
                  const float4* __restrict__ target, // B/4 float4
                  const float4* __restrict__ prev,   // B/4 float4
                  const int4*   __restrict__ dt,     // B/4 int4
                  const int4*   __restrict__ pv,     // B/4 int4
                  float* __restrict__ out)
{
    float s_center = 0.f, s_width = 0.f, s_valid = 0.f, s_dir = 0.f;

    const int tid    = blockIdx.x * NTH + threadIdx.x;
    const int stride = NBLK * NTH;                 // in vec4 units

    int  v     = tid;
    bool valid = (v < NVEC);

    float4 p0, p1, t, pc;
    int4   d, q;
    if (valid) {
        p0 = pred[2 * v];
        p1 = pred[2 * v + 1];
        t  = target[v];
        pc = prev[v];
        d  = dt[v];
        q  = pv[v];
    }

    while (valid) {
        const int  vn    = v + stride;
        const bool vmore = (vn < NVEC);

        // Prefetch next iteration's loads (predicated) BEFORE computing current.
        float4 np0, np1, nt, npc;
        int4   nd, nq;
        if (vmore) {
            np0 = pred[2 * vn];
            np1 = pred[2 * vn + 1];
            nt  = target[vn];
            npc = prev[vn];
            nd  = dt[vn];
            nq  = pv[vn];
        }

        accum_one(p0.x, p0.y, t.x, pc.x, d.x, q.x, s_center, s_width, s_valid, s_dir);
        accum_one(p0.z, p0.w, t.y, pc.y, d.y, q.y, s_center, s_width, s_valid, s_dir);
        accum_one(p1.x, p1.y, t.z, pc.z, d.z, q.z, s_center, s_width, s_valid, s_dir);
        accum_one(p1.z, p1.w, t.w, pc.w, d.w, q.w, s_center, s_width, s_valid, s_dir);

        p0 = np0; p1 = np1; t = nt; pc = npc; d = nd; q = nq;
        v = vn; valid = vmore;
    }

    // ---- intra-block reduce (float) ----
    #pragma unroll
    for (int off = 16; off > 0; off >>= 1) {
        s_center += __shfl_down_sync(0xFFFFFFFFu, s_center, off);
        s_width  += __shfl_down_sync(0xFFFFFFFFu, s_width,  off);
        s_valid  += __shfl_down_sync(0xFFFFFFFFu, s_valid,  off);
        s_dir    += __shfl_down_sync(0xFFFFFFFFu, s_dir,    off);
    }

    __shared__ float sh[4][NTH / 32];
    int lane = threadIdx.x & 31;
    int warp = threadIdx.x >> 5;
    if (lane == 0) {
        sh[0][warp] = s_center;
        sh[1][warp] = s_width;
        sh[2][warp] = s_valid;
        sh[3][warp] = s_dir;
    }
    __syncthreads();

    if (threadIdx.x == 0) {
        float c = 0.f, w = 0.f, vd = 0.f, dr = 0.f;
        #pragma unroll
        for (int i = 0; i < NTH / 32; i++) {
            c  += sh[0][i];
            w  += sh[1][i];
            vd += sh[2][i];
            dr += sh[3][i];
        }
        // Deterministic fixed-point accumulation (Q32)
        long long ic = __double2ll_rn((double)c  * FP_SCALE);
        long long iw = __double2ll_rn((double)w  * FP_SCALE);
        long long iv = __double2ll_rn((double)vd * FP_SCALE);
        long long id = __double2ll_rn((double)dr * FP_SCALE);
        atomicAdd(&g_acc[0], (unsigned long long)ic);
        atomicAdd(&g_acc[1], (unsigned long long)iw);
        atomicAdd(&g_acc[2], (unsigned long long)iv);
        atomicAdd(&g_acc[3], (unsigned long long)id);
        __threadfence();
        unsigned int prev_cnt = atomicAdd(&g_count, 1u);
        if (prev_cnt == (unsigned int)(NBLK - 1)) {
            // Last block: read 4 words, finish, reset state for next replay
            __threadfence();
            double fc = (double)(long long)g_acc[0] / FP_SCALE;
            double fw = (double)(long long)g_acc[1] / FP_SCALE;
            double fv = (double)(long long)g_acc[2] / FP_SCALE;
            double fd = (double)(long long)g_acc[3] / FP_SCALE;
            const double invn = 1.0 / (double)B_ELEMS;
            double total = (fc * invn) * 1.5 + 0.1 * (fw * invn)
                         + 10.0 * (fv * invn) + 0.5 * fd * invn;
            out[0] = (float)total;
            g_acc[0] = 0ull;
            g_acc[1] = 0ull;
            g_acc[2] = 0ull;
            g_acc[3] = 0ull;
            g_count  = 0;
        }
    }
}

extern "C" void kernel_launch(void* const* d_in, const int* in_sizes, int n_in,
                              void* d_out, int out_size) {
    const float4* pred   = (const float4*)d_in[0];
    const float4* target = (const float4*)d_in[1];
    const float4* prev   = (const float4*)d_in[2];
    const int4*   dt     = (const int4*)d_in[3];
    const int4*   pv     = (const int4*)d_in[4];
    float* out = (float*)d_out;

    loss_fused_kernel<<<NBLK, NTH>>>(pred, target, prev, dt, pv, out);
}

// round 8
// speedup vs baseline: 1.0261x; 1.0261x over previous
#include <cuda_runtime.h>
#include <cstdint>

// Problem constants
#define B_ELEMS 4194304          // 2^22 samples
#define NBLK    592              // 148 SMs * 4 CTAs -> one wave
#define NTH     256
#define NVEC    (B_ELEMS / 4)    // 2^20 vec4 groups
#define VB_BASE (NVEC / NBLK)    // 1771 vec4 per block (base)
#define VB_REM  (NVEC % NBLK)    // first 368 blocks take one extra

// Fixed-point (Q32) global accumulators: [center, width, valid, dir]
// Integer addition is exactly associative/commutative -> deterministic across
// replays regardless of block arrival order.
__device__ unsigned long long g_acc[4] = {0ull, 0ull, 0ull, 0ull};
__device__ unsigned int       g_count  = 0;

#define FP_SCALE 4294967296.0    // 2^32

__device__ __forceinline__ void accum_one(float lower, float upper,
                                          float tgt, float prev,
                                          int dt, int pv,
                                          float& s_center, float& s_width,
                                          float& s_valid, float& s_dir) {
    float center = (lower + upper) * 0.5f;
    float d = tgt - center;
    s_center = fmaf(d, d, s_center);
    s_width += (upper - lower);
    s_valid += fmaxf(lower - upper, 0.0f);
    float diff = center - prev;               // pen_up = relu(diff), pen_dn = relu(-diff)
    float sel = (pv == 0) ? diff : -diff;
    s_dir += (dt != 0) ? fmaxf(sel, 0.0f) : 0.0f;
}

// occ=4 -> 64 regs/thread: all 6 vector loads stay in flight (MLP=6).
// Balanced contiguous partition: per-SM byte load uniform to 0.06%.
__global__ void __launch_bounds__(NTH, 4)
loss_fused_kernel(const float4* __restrict__ pred,   // (B,2) -> 2 float4 per vec4 of samples
                  const float4* __restrict__ target, // B/4 float4
                  const float4* __restrict__ prev,   // B/4 float4
                  const int4*   __restrict__ dt,     // B/4 int4
                  const int4*   __restrict__ pv,     // B/4 int4
                  float* __restrict__ out)
{
    float s_center = 0.f, s_width = 0.f, s_valid = 0.f, s_dir = 0.f;

    const int b     = blockIdx.x;
    const int start = b * VB_BASE + (b < VB_REM ? b : VB_REM);
    const int end   = start + VB_BASE + (b < VB_REM ? 1 : 0);

    #pragma unroll 2
    for (int v = start + threadIdx.x; v < end; v += NTH) {
        // Front-batched loads (high MLP) — 6 x 128-bit LDG
        float4 p0 = pred[2 * v];                   // samples 4v,   4v+1 (l0,u0,l1,u1)
        float4 p1 = pred[2 * v + 1];               // samples 4v+2, 4v+3
        float4 t  = target[v];
        float4 pc = prev[v];
        int4   d  = dt[v];
        int4   q  = pv[v];

        accum_one(p0.x, p0.y, t.x, pc.x, d.x, q.x, s_center, s_width, s_valid, s_dir);
        accum_one(p0.z, p0.w, t.y, pc.y, d.y, q.y, s_center, s_width, s_valid, s_dir);
        accum_one(p1.x, p1.y, t.z, pc.z, d.z, q.z, s_center, s_width, s_valid, s_dir);
        accum_one(p1.z, p1.w, t.w, pc.w, d.w, q.w, s_center, s_width, s_valid, s_dir);
    }

    // ---- intra-block reduce (float) ----
    #pragma unroll
    for (int off = 16; off > 0; off >>= 1) {
        s_center += __shfl_down_sync(0xFFFFFFFFu, s_center, off);
        s_width  += __shfl_down_sync(0xFFFFFFFFu, s_width,  off);
        s_valid  += __shfl_down_sync(0xFFFFFFFFu, s_valid,  off);
        s_dir    += __shfl_down_sync(0xFFFFFFFFu, s_dir,    off);
    }

    __shared__ float sh[4][NTH / 32];
    int lane = threadIdx.x & 31;
    int warp = threadIdx.x >> 5;
    if (lane == 0) {
        sh[0][warp] = s_center;
        sh[1][warp] = s_width;
        sh[2][warp] = s_valid;
        sh[3][warp] = s_dir;
    }
    __syncthreads();

    if (threadIdx.x == 0) {
        float c = 0.f, w = 0.f, vd = 0.f, dr = 0.f;
        #pragma unroll
        for (int i = 0; i < NTH / 32; i++) {
            c  += sh[0][i];
            w  += sh[1][i];
            vd += sh[2][i];
            dr += sh[3][i];
        }
        // Deterministic fixed-point accumulation (Q32)
        long long ic = __double2ll_rn((double)c  * FP_SCALE);
        long long iw = __double2ll_rn((double)w  * FP_SCALE);
        long long iv = __double2ll_rn((double)vd * FP_SCALE);
        long long id = __double2ll_rn((double)dr * FP_SCALE);
        atomicAdd(&g_acc[0], (unsigned long long)ic);
        atomicAdd(&g_acc[1], (unsigned long long)iw);
        atomicAdd(&g_acc[2], (unsigned long long)iv);
        atomicAdd(&g_acc[3], (unsigned long long)id);
        __threadfence();
        unsigned int prev_cnt = atomicAdd(&g_count, 1u);
        if (prev_cnt == (unsigned int)(NBLK - 1)) {
            // Last block: read 4 words, finish, reset state for next replay
            __threadfence();
            double fc = (double)(long long)g_acc[0] / FP_SCALE;
            double fw = (double)(long long)g_acc[1] / FP_SCALE;
            double fv = (double)(long long)g_acc[2] / FP_SCALE;
            double fd = (double)(long long)g_acc[3] / FP_SCALE;
            const double invn = 1.0 / (double)B_ELEMS;
            double total = (fc * invn) * 1.5 + 0.1 * (fw * invn)
                         + 10.0 * (fv * invn) + 0.5 * fd * invn;
            out[0] = (float)total;
            g_acc[0] = 0ull;
            g_acc[1] = 0ull;
            g_acc[2] = 0ull;
            g_acc[3] = 0ull;
            g_count  = 0;
        }
    }
}

extern "C" void kernel_launch(void* const* d_in, const int* in_sizes, int n_in,
                              void* d_out, int out_size) {
    const float4* pred   = (const float4*)d_in[0];
    const float4* target = (const float4*)d_in[1];
    const float4* prev   = (const float4*)d_in[2];
    const int4*   dt     = (const int4*)d_in[3];
    const int4*   pv     = (const int4*)d_in[4];
    float* out = (float*)d_out;

    loss_fused_kernel<<<NBLK, NTH>>>(pred, target, prev, dt, pv, out);
}